// round 16
// baseline (speedup 1.0000x reference)
#include <cuda_runtime.h>
#include <math.h>

typedef unsigned long long ull;

// ---------------- problem constants ----------------
#define Bb   4
#define Cc   64
#define Hh   5
#define Ww   5
#define Kk   3
#define Ee   12
#define NHh  4
#define DHh  3
#define FFf  24
#define HOo  3
#define WOo  3
#define Ll   9
#define Ss   (Bb*Cc*Kk*Kk)       // 2304
#define ROWS (Ss*Ll)             // 20736
#define NC   (Ll*NHh)            // 36
#define YSZ  (Bb*Cc*Hh*Ww)       // 6400

#define DEG  12                  // Taylor degree: pairs j=0..12, moments M_0..M_13
#define NM   (DEG+2)             // 14 moments
#define QPB  64                  // threads per block (2 warps)
#define NCH  18                  // query chunks of 128
#define NGRP (Ll*NCH)            // 162 groups of 4 blocks

// ---------------- scratch ----------------
__device__ float4   g_ctx[NC*Ss];     // attention output per (combo, s)
__device__ unsigned g_cnt[NGRP];      // per-group arrival counters (memset to 0 each launch)

// ---------------- packed f32x2 helpers ----------------
__device__ __forceinline__ ull ffma2(ull a, ull b, ull c) {
    ull d; asm("fma.rn.f32x2 %0, %1, %2, %3;" : "=l"(d) : "l"(a), "l"(b), "l"(c)); return d;
}
__device__ __forceinline__ ull pack2(float lo, float hi) {
    ull d; asm("mov.b64 %0, {%1, %2};" : "=l"(d) : "f"(lo), "f"(hi)); return d;
}
__device__ __forceinline__ void unpack2(ull v, float& lo, float& hi) {
    asm("mov.b64 {%0, %1}, %2;" : "=f"(lo), "=f"(hi) : "l"(v));
}
__device__ __forceinline__ float ex2(float x) {
    float r; asm("ex2.approx.f32 %0, %1;" : "=f"(r) : "f"(x)); return r;
}

// ---------------- single fused kernel, per-group sync ----------------
// Block = (combo = l*4+h, chunk). Phase 1: moments + tables + attention for 128 queries.
// Group barrier over the 4 head-blocks of (l, chunk). Phase 2: post for this block's 32 rows.
__global__ void __launch_bounds__(QPB)
k_all(const float* __restrict__ x,
      const float* __restrict__ ce,
      const float* __restrict__ pe,
      const float* __restrict__ ipw,
      const float* __restrict__ ipb,
      const float* __restrict__ wo, const float* __restrict__ bo,
      const float* __restrict__ g1, const float* __restrict__ b1,
      const float* __restrict__ f1w, const float* __restrict__ f1b,
      const float* __restrict__ f2w, const float* __restrict__ f2b,
      const float* __restrict__ g2, const float* __restrict__ b2,
      const float* __restrict__ lw, const float* __restrict__ lb,
      float* __restrict__ y)
{
    // attention tables
    __shared__ ulonglong2 sTM[Cc*8];        // per c': 13 pairs {M_j/j!, M_{j+1}/j!} + pad (128B)
    __shared__ float4 sTB[Cc*2];            // per c': {b*log2e, 0}, {v0, 0}
    __shared__ float4 sTA[Cc];              // per c: {a0,a1,a2, gamma}
    __shared__ float  sUW[8];               // {u0,u1,u2, delta, wv0,wv1,wv2, -}
    // post weights
    __shared__ float swo[Ee*Ee], sbo[Ee], sg1[Ee], sb1[Ee];
    __shared__ float s1[FFf*Ee], s1b[FFf], s2[Ee*FFf], s2b[Ee];
    __shared__ float sg2[Ee], sb2[Ee], slw[Ee], slb;

    int combo = blockIdx.x;
    int l = combo >> 2, h = combo & 3;
    int chunk = blockIdx.y;
    int tid = threadIdx.x;
    int oi = l/WOo, oj = l%WOo;
    const unsigned FULL = 0xFFFFFFFFu;

    // ---- post-weight preload (hides under prologue compute) ----
    for (int i = tid; i < Ee*Ee; i += QPB) swo[i] = wo[i];
    for (int i = tid; i < FFf*Ee; i += QPB) { s1[i] = f1w[i]; s2[i] = f2w[i]; }
    if (tid < FFf) s1b[tid] = f1b[tid];
    if (tid < Ee) {
        sbo[tid] = bo[tid];  sg1[tid] = g1[tid];  sb1[tid] = b1[tid];
        s2b[tid] = f2b[tid]; sg2[tid] = g2[tid];  sb2[tid] = b2[tid];
        slw[tid] = lw[tid];
    }
    if (tid == 0) slb = lb[0];

    // ---- moments: one thread per channel, 36 samples (fp32) ----
    {
        int ch = tid;
        float m[NM];
        #pragma unroll
        for (int k = 0; k < NM; k++) m[k] = 0.f;

        #pragma unroll
        for (int b = 0; b < Bb; b++) {
            #pragma unroll
            for (int p = 0; p < 9; p++) {
                float xv = x[((b*Cc + ch)*Hh + (p/3) + oi)*Ww + (p%3) + oj];
                float pw = 1.f;
                #pragma unroll
                for (int k = 0; k < NM; k++) { m[k] += pw; pw *= xv; }
            }
        }
        float* dst = (float*)&sTM[ch*8];
        float invf = 1.f;
        #pragma unroll
        for (int j = 0; j <= DEG; j++) {
            if (j > 0) invf /= (float)j;      // 1/j!
            dst[2*j]   = m[j]   * invf;
            dst[2*j+1] = m[j+1] * invf;
        }
        #pragma unroll
        for (int j = 2*DEG+2; j < 32; j++) dst[j] = 0.f;
    }

    // ---- tables: one thread per channel, this block's head ----
    const float IS3 = 0.57735026918962576f;   // 1/sqrt(3)
    const float L2E = 1.4426950408889634f;
    {
        int c = tid;
        float rc[Ee];
        #pragma unroll
        for (int f = 0; f < Ee; f++) rc[f] = ce[c*Ee + f] + pe[l*Ee + f];

        float a[3], b[3], v0[3], w[3];
        #pragma unroll
        for (int d = 0; d < 3; d++) {
            const float* Wq = ipw + (3*h + d)*Ee;
            const float* Wk = ipw + (Ee + 3*h + d)*Ee;
            const float* Wv = ipw + (2*Ee + 3*h + d)*Ee;
            float aq = ipb[3*h + d];
            float ak = ipb[Ee + 3*h + d];
            float av = ipb[2*Ee + 3*h + d];
            float uk = 0.f;
            #pragma unroll
            for (int f = 0; f < Ee; f++) {
                aq += Wq[f]*rc[f]; ak += Wk[f]*rc[f]; av += Wv[f]*rc[f];
                uk += Wk[f];
            }
            a[d] = aq*IS3; b[d] = ak; v0[d] = av; w[d] = uk;
        }
        float gamma = a[0]*w[0] + a[1]*w[1] + a[2]*w[2];
        sTA[c] = make_float4(a[0], a[1], a[2], gamma);
        sTB[c*2 + 0] = make_float4(b[0]*L2E, b[1]*L2E, b[2]*L2E, 0.f);
        sTB[c*2 + 1] = make_float4(v0[0], v0[1], v0[2], 0.f);
    }
    if (tid == 0) {
        float u[3], w[3], wv[3];
        #pragma unroll
        for (int d = 0; d < 3; d++) {
            float uq = 0.f, uk = 0.f, uv = 0.f;
            #pragma unroll
            for (int f = 0; f < Ee; f++) {
                uq += ipw[(3*h + d)*Ee + f];
                uk += ipw[(Ee + 3*h + d)*Ee + f];
                uv += ipw[(2*Ee + 3*h + d)*Ee + f];
            }
            u[d] = uq*IS3; w[d] = uk; wv[d] = uv;
        }
        sUW[0] = u[0]; sUW[1] = u[1]; sUW[2] = u[2];
        sUW[3] = u[0]*w[0] + u[1]*w[1] + u[2]*w[2];   // delta
        sUW[4] = wv[0]; sUW[5] = wv[1]; sUW[6] = wv[2];
    }
    __syncthreads();

    // ---- attention main loop: 2 queries per thread (R13 structure) ----
    int sA = chunk*(2*QPB) + tid;
    int sB = sA + QPB;

    int biA = sA / (Cc*9), remA = sA % (Cc*9);
    int cA = remA / 9, pA = remA % 9;
    float xvA = x[((biA*Cc + cA)*Hh + (pA/3) + oi)*Ww + (pA%3) + oj];

    int biB = sB / (Cc*9), remB = sB % (Cc*9);
    int cB = remB / 9, pB = remB % 9;
    float xvB = x[((biB*Cc + cB)*Hh + (pB/3) + oi)*Ww + (pB%3) + oj];

    float u0 = sUW[0], u1 = sUW[1], u2 = sUW[2], delta = sUW[3];
    float wv0 = sUW[4], wv1 = sUW[5], wv2 = sUW[6];

    float4 agA = sTA[cA];
    float qA0 = agA.x + xvA*u0, qA1 = agA.y + xvA*u1, qA2 = agA.z + xvA*u2;
    float gA  = agA.w + xvA*delta;
    ull  gpkA = pack2(gA, gA);

    float4 agB = sTA[cB];
    float qB0 = agB.x + xvB*u0, qB1 = agB.y + xvB*u1, qB2 = agB.z + xvB*u2;
    float gB  = agB.w + xvB*delta;
    ull  gpkB = pack2(gB, gB);

    float denA = 0.f, oA0 = 0.f, oA1 = 0.f, oA2 = 0.f;
    float denB = 0.f, oB0 = 0.f, oB1 = 0.f, oB2 = 0.f;

    #pragma unroll 2
    for (int cp = 0; cp < Cc; cp++) {
        float4 bb = sTB[cp*2];
        float4 vv = sTB[cp*2 + 1];
        const ull* Cp = (const ull*)&sTM[cp*8];

        float eargA = fmaf(qA0, bb.x, fmaf(qA1, bb.y, qA2*bb.z));   // pre-scaled *log2e
        float eargB = fmaf(qB0, bb.x, fmaf(qB1, bb.y, qB2*bb.z));
        float EA = ex2(eargA);
        float EB = ex2(eargB);

        ull accA = Cp[DEG];
        ull accB = Cp[DEG];
        #pragma unroll
        for (int j = DEG-1; j >= 0; j--) {
            accA = ffma2(accA, gpkA, Cp[j]);
            accB = ffma2(accB, gpkB, Cp[j]);
        }
        float S0A, S1A; unpack2(accA, S0A, S1A);
        float S0B, S1B; unpack2(accB, S0B, S1B);

        float ESA0 = EA*S0A, ESA1 = EA*S1A;
        denA += ESA0;
        oA0 = fmaf(ESA1, wv0, fmaf(ESA0, vv.x, oA0));
        oA1 = fmaf(ESA1, wv1, fmaf(ESA0, vv.y, oA1));
        oA2 = fmaf(ESA1, wv2, fmaf(ESA0, vv.z, oA2));

        float ESB0 = EB*S0B, ESB1 = EB*S1B;
        denB += ESB0;
        oB0 = fmaf(ESB1, wv0, fmaf(ESB0, vv.x, oB0));
        oB1 = fmaf(ESB1, wv1, fmaf(ESB0, vv.y, oB1));
        oB2 = fmaf(ESB1, wv2, fmaf(ESB0, vv.z, oB2));
    }

    float invA = 1.f / denA;
    float invB = 1.f / denB;
    g_ctx[combo*Ss + sA] = make_float4(oA0*invA, oA1*invA, oA2*invA, 0.f);
    g_ctx[combo*Ss + sB] = make_float4(oB0*invB, oB1*invB, oB2*invB, 0.f);

    // ---- group barrier: the 4 head-blocks of (l, chunk) ----
    __syncthreads();
    if (tid == 0) {
        int gid = l*NCH + chunk;
        __threadfence();
        atomicAdd(&g_cnt[gid], 1u);
        while (*(volatile unsigned*)&g_cnt[gid] < 4u) { __nanosleep(32); }
    }
    __syncthreads();

    // ---- phase 2: post for this block's 32 rows (2 passes, quad-split) ----
    int q = tid & 3;
    int ebase = q*3;

    #pragma unroll
    for (int pass = 0; pass < 2; pass++) {
        int s = chunk*128 + h*32 + pass*16 + (tid >> 2);

        float cx[Ee];
        #pragma unroll
        for (int hh = 0; hh < NHh; hh++) {
            float4 o = g_ctx[(l*NHh + hh)*Ss + s];
            cx[hh*3] = o.x; cx[hh*3+1] = o.y; cx[hh*3+2] = o.z;
        }

        int bi = s / (Cc*9);
        int rem = s % (Cc*9);
        int c = rem / 9, p = rem % 9;
        int pi = p/3, pj = p%3;
        float xv = x[((bi*Cc + c)*Hh + pi + oi)*Ww + pj + oj];

        float t[3];
        #pragma unroll
        for (int eo = 0; eo < 3; eo++) {
            int e = ebase + eo;
            float acc = sbo[e];
            #pragma unroll
            for (int f = 0; f < Ee; f++) acc += cx[f] * swo[e*Ee + f];
            t[eo] = (__ldg(&ce[c*Ee + e]) + __ldg(&pe[l*Ee + e]) + xv) + acc;
        }

        float sl = t[0] + t[1] + t[2];
        sl += __shfl_xor_sync(FULL, sl, 1);
        sl += __shfl_xor_sync(FULL, sl, 2);
        float mu = sl * (1.f/Ee);
        float vl = 0.f;
        #pragma unroll
        for (int eo = 0; eo < 3; eo++) { float d = t[eo]-mu; vl += d*d; }
        vl += __shfl_xor_sync(FULL, vl, 1);
        vl += __shfl_xor_sync(FULL, vl, 2);
        float rs = rsqrtf(vl*(1.f/Ee) + 1e-5f);

        float h1[3];
        #pragma unroll
        for (int eo = 0; eo < 3; eo++) {
            int e = ebase + eo;
            h1[eo] = (t[eo]-mu)*rs*sg1[e] + sb1[e];
        }

        float hid[FFf];
        #pragma unroll
        for (int f = 0; f < FFf; f++) {
            float pd = h1[0]*s1[f*Ee + ebase] + h1[1]*s1[f*Ee + ebase + 1] + h1[2]*s1[f*Ee + ebase + 2];
            pd += __shfl_xor_sync(FULL, pd, 1);
            pd += __shfl_xor_sync(FULL, pd, 2);
            hid[f] = fmaxf(pd + s1b[f], 0.f);
        }

        float t2[3];
        #pragma unroll
        for (int eo = 0; eo < 3; eo++) {
            int e = ebase + eo;
            float acc = s2b[e];
            #pragma unroll
            for (int f = 0; f < FFf; f++) acc += hid[f] * s2[e*FFf + f];
            t2[eo] = h1[eo] + acc;
        }

        float sl2 = t2[0] + t2[1] + t2[2];
        sl2 += __shfl_xor_sync(FULL, sl2, 1);
        sl2 += __shfl_xor_sync(FULL, sl2, 2);
        float mu2 = sl2 * (1.f/Ee);
        float vl2 = 0.f;
        #pragma unroll
        for (int eo = 0; eo < 3; eo++) { float d = t2[eo]-mu2; vl2 += d*d; }
        vl2 += __shfl_xor_sync(FULL, vl2, 1);
        vl2 += __shfl_xor_sync(FULL, vl2, 2);
        float rs2 = rsqrtf(vl2*(1.f/Ee) + 1e-5f);

        float plin = 0.f;
        #pragma unroll
        for (int eo = 0; eo < 3; eo++) {
            int e = ebase + eo;
            plin += ((t2[eo]-mu2)*rs2*sg2[e] + sb2[e]) * slw[e];
        }
        plin += __shfl_xor_sync(FULL, plin, 1);
        plin += __shfl_xor_sync(FULL, plin, 2);

        if (q == 0) {
            float proj = slb + plin;
            atomicAdd(&y[((bi*Cc + c)*Hh + (pi+oi))*Ww + (pj+oj)], proj);
        }
    }
}

// ---------------- launch ----------------
extern "C" void kernel_launch(void* const* d_in, const int* in_sizes, int n_in,
                              void* d_out, int out_size)
{
    const float* x    = (const float*)d_in[0];
    const float* ce   = (const float*)d_in[1];
    const float* pe   = (const float*)d_in[2];
    const float* ipw  = (const float*)d_in[3];
    const float* ipb  = (const float*)d_in[4];
    const float* opw  = (const float*)d_in[5];
    const float* opb  = (const float*)d_in[6];
    const float* ln1w = (const float*)d_in[7];
    const float* ln1b = (const float*)d_in[8];
    const float* f1w  = (const float*)d_in[9];
    const float* f1b  = (const float*)d_in[10];
    const float* f2w  = (const float*)d_in[11];
    const float* f2b  = (const float*)d_in[12];
    const float* ln2w = (const float*)d_in[13];
    const float* ln2b = (const float*)d_in[14];
    const float* lw   = (const float*)d_in[15];
    const float* lb   = (const float*)d_in[16];
    float* y = (float*)d_out;

    void* cntPtr = nullptr;
    cudaGetSymbolAddress(&cntPtr, g_cnt);
    cudaMemsetAsync(cntPtr, 0, NGRP*sizeof(unsigned));
    cudaMemsetAsync(y, 0, YSZ*sizeof(float));

    dim3 grid(NC, NCH);
    k_all<<<grid, QPB>>>(x, ce, pe, ipw, ipb, opw, opb, ln1w, ln1b,
                         f1w, f1b, f2w, f2b, ln2w, ln2b, lw, lb, y);
}

// round 17
// speedup vs baseline: 1.1417x; 1.1417x over previous
#include <cuda_runtime.h>
#include <math.h>

typedef unsigned long long ull;

// ---------------- problem constants ----------------
#define Bb   4
#define Cc   64
#define Hh   5
#define Ww   5
#define Kk   3
#define Ee   12
#define NHh  4
#define DHh  3
#define FFf  24
#define HOo  3
#define WOo  3
#define Ll   9
#define Ss   (Bb*Cc*Kk*Kk)       // 2304
#define ROWS (Ss*Ll)             // 20736
#define NC   (Ll*NHh)            // 36
#define YSZ  (Bb*Cc*Hh*Ww)       // 6400

#define DEG  12                  // Taylor degree: pairs j=0..12, moments M_0..M_13
#define NM   (DEG+2)             // 14 moments
#define QPB  128                 // threads per block (4 warps)
#define NCH  18                  // query chunks of 128
#define NGRP (Ll*NCH)            // 162 groups of 4 blocks

// ---------------- scratch ----------------
__device__ float4   g_ctx[NC*Ss];     // attention output per (combo, s)
__device__ unsigned g_cnt[NGRP];      // per-group arrival counters (memset to 0 each launch)

// ---------------- packed f32x2 helpers ----------------
__device__ __forceinline__ ull ffma2(ull a, ull b, ull c) {
    ull d; asm("fma.rn.f32x2 %0, %1, %2, %3;" : "=l"(d) : "l"(a), "l"(b), "l"(c)); return d;
}
__device__ __forceinline__ ull pack2(float lo, float hi) {
    ull d; asm("mov.b64 %0, {%1, %2};" : "=l"(d) : "f"(lo), "f"(hi)); return d;
}
__device__ __forceinline__ void unpack2(ull v, float& lo, float& hi) {
    asm("mov.b64 {%0, %1}, %2;" : "=f"(lo), "=f"(hi) : "l"(v));
}
__device__ __forceinline__ float ex2(float x) {
    float r; asm("ex2.approx.f32 %0, %1;" : "=f"(r) : "f"(x)); return r;
}

// ---------------- single fused kernel, channel-split + per-group sync ----------------
// Block = (combo = l*4+h, chunk of 128 queries), 128 threads:
//   half = tid>>6 selects channel range [half*32, half*32+32); t64 = tid&63 selects query pair.
// Phase 1: moments + tables + attention partials; smem combine across halves.
// Group barrier over the 4 head-blocks of (l, chunk). Phase 2: post for 32 rows (1 pass).
__global__ void __launch_bounds__(QPB)
k_all(const float* __restrict__ x,
      const float* __restrict__ ce,
      const float* __restrict__ pe,
      const float* __restrict__ ipw,
      const float* __restrict__ ipb,
      const float* __restrict__ wo, const float* __restrict__ bo,
      const float* __restrict__ g1, const float* __restrict__ b1,
      const float* __restrict__ f1w, const float* __restrict__ f1b,
      const float* __restrict__ f2w, const float* __restrict__ f2b,
      const float* __restrict__ g2, const float* __restrict__ b2,
      const float* __restrict__ lw, const float* __restrict__ lb,
      float* __restrict__ y)
{
    // attention tables
    __shared__ ulonglong2 sTM[Cc*8];        // per c': 13 pairs {M_j/j!, M_{j+1}/j!} + pad (128B)
    __shared__ float4 sTB[Cc*2];            // per c': {b*log2e, 0}, {v0, 0}
    __shared__ float4 sTA[Cc];              // per c: {a0,a1,a2, gamma}
    __shared__ float  sUW[8];               // {u0,u1,u2, delta, wv0,wv1,wv2, -}
    __shared__ float4 sP[2][QPB/2];         // partials from half 1: [queryA/B][t64]
    // post weights
    __shared__ float swo[Ee*Ee], sbo[Ee], sg1[Ee], sb1[Ee];
    __shared__ float s1[FFf*Ee], s1b[FFf], s2[Ee*FFf], s2b[Ee];
    __shared__ float sg2[Ee], sb2[Ee], slw[Ee], slb;

    int combo = blockIdx.x;
    int l = combo >> 2, h = combo & 3;
    int chunk = blockIdx.y;
    int tid = threadIdx.x;
    int oi = l/WOo, oj = l%WOo;
    const unsigned FULL = 0xFFFFFFFFu;

    // ---- post-weight preload (hides under prologue compute) ----
    for (int i = tid; i < Ee*Ee; i += QPB) swo[i] = wo[i];
    for (int i = tid; i < FFf*Ee; i += QPB) { s1[i] = f1w[i]; s2[i] = f2w[i]; }
    if (tid < FFf) s1b[tid] = f1b[tid];
    if (tid < Ee) {
        sbo[tid] = bo[tid];  sg1[tid] = g1[tid];  sb1[tid] = b1[tid];
        s2b[tid] = f2b[tid]; sg2[tid] = g2[tid];  sb2[tid] = b2[tid];
        slw[tid] = lw[tid];
    }
    if (tid == 0) slb = lb[0];

    // ---- moments: 2 threads per channel, 18 samples each (fp32) ----
    {
        int ch = tid >> 1, hf = tid & 1;
        float m[NM];
        #pragma unroll
        for (int k = 0; k < NM; k++) m[k] = 0.f;

        #pragma unroll
        for (int bb = 0; bb < 2; bb++) {
            int b = hf*2 + bb;
            #pragma unroll
            for (int p = 0; p < 9; p++) {
                float xv = x[((b*Cc + ch)*Hh + (p/3) + oi)*Ww + (p%3) + oj];
                float pw = 1.f;
                #pragma unroll
                for (int k = 0; k < NM; k++) { m[k] += pw; pw *= xv; }
            }
        }
        #pragma unroll
        for (int k = 0; k < NM; k++) m[k] += __shfl_xor_sync(FULL, m[k], 1);

        if (hf == 0) {
            float* dst = (float*)&sTM[ch*8];
            float invf = 1.f;
            #pragma unroll
            for (int j = 0; j <= DEG; j++) {
                if (j > 0) invf /= (float)j;      // 1/j!
                dst[2*j]   = m[j]   * invf;
                dst[2*j+1] = m[j+1] * invf;
            }
            #pragma unroll
            for (int j = 2*DEG+2; j < 32; j++) dst[j] = 0.f;
        }
    }

    // ---- tables: threads 0-63 = one channel each; thread 64 = per-combo sums ----
    const float IS3 = 0.57735026918962576f;   // 1/sqrt(3)
    const float L2E = 1.4426950408889634f;
    if (tid < Cc) {
        int c = tid;
        float rc[Ee];
        #pragma unroll
        for (int f = 0; f < Ee; f++) rc[f] = ce[c*Ee + f] + pe[l*Ee + f];

        float a[3], b[3], v0[3], w[3];
        #pragma unroll
        for (int d = 0; d < 3; d++) {
            const float* Wq = ipw + (3*h + d)*Ee;
            const float* Wk = ipw + (Ee + 3*h + d)*Ee;
            const float* Wv = ipw + (2*Ee + 3*h + d)*Ee;
            float aq = ipb[3*h + d];
            float ak = ipb[Ee + 3*h + d];
            float av = ipb[2*Ee + 3*h + d];
            float uk = 0.f;
            #pragma unroll
            for (int f = 0; f < Ee; f++) {
                aq += Wq[f]*rc[f]; ak += Wk[f]*rc[f]; av += Wv[f]*rc[f];
                uk += Wk[f];
            }
            a[d] = aq*IS3; b[d] = ak; v0[d] = av; w[d] = uk;
        }
        float gamma = a[0]*w[0] + a[1]*w[1] + a[2]*w[2];
        sTA[c] = make_float4(a[0], a[1], a[2], gamma);
        sTB[c*2 + 0] = make_float4(b[0]*L2E, b[1]*L2E, b[2]*L2E, 0.f);
        sTB[c*2 + 1] = make_float4(v0[0], v0[1], v0[2], 0.f);
    } else if (tid == Cc) {
        float u[3], w[3], wv[3];
        #pragma unroll
        for (int d = 0; d < 3; d++) {
            float uq = 0.f, uk = 0.f, uv = 0.f;
            #pragma unroll
            for (int f = 0; f < Ee; f++) {
                uq += ipw[(3*h + d)*Ee + f];
                uk += ipw[(Ee + 3*h + d)*Ee + f];
                uv += ipw[(2*Ee + 3*h + d)*Ee + f];
            }
            u[d] = uq*IS3; w[d] = uk; wv[d] = uv;
        }
        sUW[0] = u[0]; sUW[1] = u[1]; sUW[2] = u[2];
        sUW[3] = u[0]*w[0] + u[1]*w[1] + u[2]*w[2];   // delta
        sUW[4] = wv[0]; sUW[5] = wv[1]; sUW[6] = wv[2];
    }
    __syncthreads();

    // ---- attention: 2 queries per thread, 32 channels per half ----
    int half = tid >> 6;
    int t64  = tid & 63;
    int cbase = half*32;

    int sA = chunk*128 + t64;
    int sB = sA + 64;

    int biA = sA / (Cc*9), remA = sA % (Cc*9);
    int cA = remA / 9, pA = remA % 9;
    float xvA = x[((biA*Cc + cA)*Hh + (pA/3) + oi)*Ww + (pA%3) + oj];

    int biB = sB / (Cc*9), remB = sB % (Cc*9);
    int cB = remB / 9, pB = remB % 9;
    float xvB = x[((biB*Cc + cB)*Hh + (pB/3) + oi)*Ww + (pB%3) + oj];

    float u0 = sUW[0], u1 = sUW[1], u2 = sUW[2], delta = sUW[3];
    float wv0 = sUW[4], wv1 = sUW[5], wv2 = sUW[6];

    float4 agA = sTA[cA];
    float qA0 = agA.x + xvA*u0, qA1 = agA.y + xvA*u1, qA2 = agA.z + xvA*u2;
    float gA  = agA.w + xvA*delta;
    ull  gpkA = pack2(gA, gA);

    float4 agB = sTA[cB];
    float qB0 = agB.x + xvB*u0, qB1 = agB.y + xvB*u1, qB2 = agB.z + xvB*u2;
    float gB  = agB.w + xvB*delta;
    ull  gpkB = pack2(gB, gB);

    float denA = 0.f, oA0 = 0.f, oA1 = 0.f, oA2 = 0.f;
    float denB = 0.f, oB0 = 0.f, oB1 = 0.f, oB2 = 0.f;

    #pragma unroll 2
    for (int cc = 0; cc < 32; cc++) {
        int cp = cbase + cc;
        float4 bb = sTB[cp*2];
        float4 vv = sTB[cp*2 + 1];
        const ull* Cp = (const ull*)&sTM[cp*8];

        float eargA = fmaf(qA0, bb.x, fmaf(qA1, bb.y, qA2*bb.z));   // pre-scaled *log2e
        float eargB = fmaf(qB0, bb.x, fmaf(qB1, bb.y, qB2*bb.z));
        float EA = ex2(eargA);
        float EB = ex2(eargB);

        ull accA = Cp[DEG];
        ull accB = Cp[DEG];
        #pragma unroll
        for (int j = DEG-1; j >= 0; j--) {
            accA = ffma2(accA, gpkA, Cp[j]);
            accB = ffma2(accB, gpkB, Cp[j]);
        }
        float S0A, S1A; unpack2(accA, S0A, S1A);
        float S0B, S1B; unpack2(accB, S0B, S1B);

        float ESA0 = EA*S0A, ESA1 = EA*S1A;
        denA += ESA0;
        oA0 = fmaf(ESA1, wv0, fmaf(ESA0, vv.x, oA0));
        oA1 = fmaf(ESA1, wv1, fmaf(ESA0, vv.y, oA1));
        oA2 = fmaf(ESA1, wv2, fmaf(ESA0, vv.z, oA2));

        float ESB0 = EB*S0B, ESB1 = EB*S1B;
        denB += ESB0;
        oB0 = fmaf(ESB1, wv0, fmaf(ESB0, vv.x, oB0));
        oB1 = fmaf(ESB1, wv1, fmaf(ESB0, vv.y, oB1));
        oB2 = fmaf(ESB1, wv2, fmaf(ESB0, vv.z, oB2));
    }

    // ---- combine halves via smem ----
    if (half == 1) {
        sP[0][t64] = make_float4(denA, oA0, oA1, oA2);
        sP[1][t64] = make_float4(denB, oB0, oB1, oB2);
    }
    __syncthreads();
    if (half == 0) {
        float4 pA4 = sP[0][t64];
        float4 pB4 = sP[1][t64];
        float dA = denA + pA4.x, a0 = oA0 + pA4.y, a1 = oA1 + pA4.z, a2 = oA2 + pA4.w;
        float dB = denB + pB4.x, b0 = oB0 + pB4.y, b1 = oB1 + pB4.z, b2 = oB2 + pB4.w;
        float invA = 1.f / dA;
        float invB = 1.f / dB;
        g_ctx[combo*Ss + sA] = make_float4(a0*invA, a1*invA, a2*invA, 0.f);
        g_ctx[combo*Ss + sB] = make_float4(b0*invB, b1*invB, b2*invB, 0.f);
    }

    // ---- group barrier: the 4 head-blocks of (l, chunk) ----
    __syncthreads();
    if (tid == 0) {
        int gid = l*NCH + chunk;
        __threadfence();
        atomicAdd(&g_cnt[gid], 1u);
        while (*(volatile unsigned*)&g_cnt[gid] < 4u) { __nanosleep(32); }
    }
    __syncthreads();

    // ---- phase 2: post for this block's 32 rows (single pass, quad-split) ----
    int q = tid & 3;
    int ebase = q*3;
    {
        int s = chunk*128 + h*32 + (tid >> 2);

        float cx[Ee];
        #pragma unroll
        for (int hh = 0; hh < NHh; hh++) {
            float4 o = g_ctx[(l*NHh + hh)*Ss + s];
            cx[hh*3] = o.x; cx[hh*3+1] = o.y; cx[hh*3+2] = o.z;
        }

        int bi = s / (Cc*9);
        int rem = s % (Cc*9);
        int c = rem / 9, p = rem % 9;
        int pi = p/3, pj = p%3;
        float xv = x[((bi*Cc + c)*Hh + pi + oi)*Ww + pj + oj];

        float t[3];
        #pragma unroll
        for (int eo = 0; eo < 3; eo++) {
            int e = ebase + eo;
            float acc = sbo[e];
            #pragma unroll
            for (int f = 0; f < Ee; f++) acc += cx[f] * swo[e*Ee + f];
            t[eo] = (__ldg(&ce[c*Ee + e]) + __ldg(&pe[l*Ee + e]) + xv) + acc;
        }

        float sl = t[0] + t[1] + t[2];
        sl += __shfl_xor_sync(FULL, sl, 1);
        sl += __shfl_xor_sync(FULL, sl, 2);
        float mu = sl * (1.f/Ee);
        float vl = 0.f;
        #pragma unroll
        for (int eo = 0; eo < 3; eo++) { float d = t[eo]-mu; vl += d*d; }
        vl += __shfl_xor_sync(FULL, vl, 1);
        vl += __shfl_xor_sync(FULL, vl, 2);
        float rs = rsqrtf(vl*(1.f/Ee) + 1e-5f);

        float h1[3];
        #pragma unroll
        for (int eo = 0; eo < 3; eo++) {
            int e = ebase + eo;
            h1[eo] = (t[eo]-mu)*rs*sg1[e] + sb1[e];
        }

        float hid[FFf];
        #pragma unroll
        for (int f = 0; f < FFf; f++) {
            float pd = h1[0]*s1[f*Ee + ebase] + h1[1]*s1[f*Ee + ebase + 1] + h1[2]*s1[f*Ee + ebase + 2];
            pd += __shfl_xor_sync(FULL, pd, 1);
            pd += __shfl_xor_sync(FULL, pd, 2);
            hid[f] = fmaxf(pd + s1b[f], 0.f);
        }

        float t2[3];
        #pragma unroll
        for (int eo = 0; eo < 3; eo++) {
            int e = ebase + eo;
            float acc = s2b[e];
            #pragma unroll
            for (int f = 0; f < FFf; f++) acc += hid[f] * s2[e*FFf + f];
            t2[eo] = h1[eo] + acc;
        }

        float sl2 = t2[0] + t2[1] + t2[2];
        sl2 += __shfl_xor_sync(FULL, sl2, 1);
        sl2 += __shfl_xor_sync(FULL, sl2, 2);
        float mu2 = sl2 * (1.f/Ee);
        float vl2 = 0.f;
        #pragma unroll
        for (int eo = 0; eo < 3; eo++) { float d = t2[eo]-mu2; vl2 += d*d; }
        vl2 += __shfl_xor_sync(FULL, vl2, 1);
        vl2 += __shfl_xor_sync(FULL, vl2, 2);
        float rs2 = rsqrtf(vl2*(1.f/Ee) + 1e-5f);

        float plin = 0.f;
        #pragma unroll
        for (int eo = 0; eo < 3; eo++) {
            int e = ebase + eo;
            plin += ((t2[eo]-mu2)*rs2*sg2[e] + sb2[e]) * slw[e];
        }
        plin += __shfl_xor_sync(FULL, plin, 1);
        plin += __shfl_xor_sync(FULL, plin, 2);

        if (q == 0) {
            float proj = slb + plin;
            atomicAdd(&y[((bi*Cc + c)*Hh + (pi+oi))*Ww + (pj+oj)], proj);
        }
    }
}

// ---------------- launch ----------------
extern "C" void kernel_launch(void* const* d_in, const int* in_sizes, int n_in,
                              void* d_out, int out_size)
{
    const float* x    = (const float*)d_in[0];
    const float* ce   = (const float*)d_in[1];
    const float* pe   = (const float*)d_in[2];
    const float* ipw  = (const float*)d_in[3];
    const float* ipb  = (const float*)d_in[4];
    const float* opw  = (const float*)d_in[5];
    const float* opb  = (const float*)d_in[6];
    const float* ln1w = (const float*)d_in[7];
    const float* ln1b = (const float*)d_in[8];
    const float* f1w  = (const float*)d_in[9];
    const float* f1b  = (const float*)d_in[10];
    const float* f2w  = (const float*)d_in[11];
    const float* f2b  = (const float*)d_in[12];
    const float* ln2w = (const float*)d_in[13];
    const float* ln2b = (const float*)d_in[14];
    const float* lw   = (const float*)d_in[15];
    const float* lb   = (const float*)d_in[16];
    float* y = (float*)d_out;

    void* cntPtr = nullptr;
    cudaGetSymbolAddress(&cntPtr, g_cnt);
    cudaMemsetAsync(cntPtr, 0, NGRP*sizeof(unsigned));
    cudaMemsetAsync(y, 0, YSZ*sizeof(float));

    dim3 grid(NC, NCH);
    k_all<<<grid, QPB>>>(x, ce, pe, ipw, ipb, opw, opb, ln1w, ln1b,
                         f1w, f1b, f2w, f2b, ln2w, ln2b, lw, lb, y);
}